// round 15
// baseline (speedup 1.0000x reference)
#include <cuda_runtime.h>
#include <cuda_fp16.h>
#include <math_constants.h>
#include <cstdint>

#define S_LEN  2048
#define D_DIM  1024
#define N_H    16
#define M_ROWS 4096

// ------------------------- device scratch (bss) ----------------------------
#define DEVBUF __device__ __align__(256)
DEVBUF __half g_hid[M_ROWS * D_DIM];       // fp16, natural [row][k]
DEVBUF __half g_wt [4 * D_DIM * D_DIM];    // W^T [n][k] fp16
DEVBUF __half g_q  [M_ROWS * D_DIM];       // [token][1024]
DEVBUF __half g_k  [M_ROWS * D_DIM];
DEVBUF __half g_vt [32 * 64 * S_LEN];      // [bh][d][token]
DEVBUF __half g_ctx[M_ROWS * D_DIM];
DEVBUF float  g_mbias[2 * S_LEN];          // mask ? 0 : -1e30

// ------------------------------ helpers ------------------------------------
__device__ __forceinline__ uint32_t smem_u32(const void* p) {
    return (uint32_t)__cvta_generic_to_shared(p);
}
__device__ __forceinline__ void ldm4(uint32_t* r, uint32_t a) {
    asm volatile("ldmatrix.sync.aligned.m8n8.x4.shared.b16 {%0,%1,%2,%3}, [%4];"
                 : "=r"(r[0]), "=r"(r[1]), "=r"(r[2]), "=r"(r[3]) : "r"(a));
}
__device__ __forceinline__ void mma_fp16(float* c, const uint32_t* a,
                                         uint32_t b0, uint32_t b1) {
    asm volatile("mma.sync.aligned.m16n8k16.row.col.f32.f16.f16.f32 "
                 "{%0,%1,%2,%3}, {%4,%5,%6,%7}, {%8,%9}, {%0,%1,%2,%3};"
                 : "+f"(c[0]), "+f"(c[1]), "+f"(c[2]), "+f"(c[3])
                 : "r"(a[0]), "r"(a[1]), "r"(a[2]), "r"(a[3]), "r"(b0), "r"(b1));
}
__device__ __forceinline__ void cpa(void* d, const void* s) {
    asm volatile("cp.async.cg.shared.global [%0], [%1], 16;"
                 :: "r"(smem_u32(d)), "l"(s));
}
__device__ __forceinline__ void cp_commit() { asm volatile("cp.async.commit_group;"); }
template<int N> __device__ __forceinline__ void cp_wait() {
    asm volatile("cp.async.wait_group %0;" :: "n"(N));
}
__device__ __forceinline__ void stg_cs2(float* p, float x, float y) {
    asm volatile("st.global.cs.v2.f32 [%0], {%1, %2};"
                 :: "l"(p), "f"(x), "f"(y) : "memory");
}
__device__ __forceinline__ uint32_t packh2(float x, float y) {
    __half2 h = __floats2half2_rn(x, y);
    return *(uint32_t*)&h;
}

// ---------------------------------------------------------------------------
// prep: fp32 -> fp16 hidden (+ mask bias); transpose + fp16 weights
// ---------------------------------------------------------------------------
__global__ __launch_bounds__(256)
void prep_hid(const float4* __restrict__ in, uint4* __restrict__ out, int ng,
              const int* __restrict__ mask, float* __restrict__ mbias, int nb)
{
    int i = blockIdx.x * 256 + threadIdx.x;
    if (i < ng) {
        float4 v0 = in[i * 2], v1 = in[i * 2 + 1];
        __half2 h0 = __floats2half2_rn(v0.x, v0.y);
        __half2 h1 = __floats2half2_rn(v0.z, v0.w);
        __half2 h2 = __floats2half2_rn(v1.x, v1.y);
        __half2 h3 = __floats2half2_rn(v1.z, v1.w);
        uint4 o;
        o.x = *(uint32_t*)&h0; o.y = *(uint32_t*)&h1;
        o.z = *(uint32_t*)&h2; o.w = *(uint32_t*)&h3;
        out[i] = o;
    }
    int j = i - ng;
    if (j >= 0 && j < nb) mbias[j] = mask[j] ? 0.f : -1e30f;
}

__global__ __launch_bounds__(256)
void prep_w(const float* __restrict__ W0, const float* __restrict__ W1,
            const float* __restrict__ W2, const float* __restrict__ W3,
            __half* __restrict__ outbase)
{
    __shared__ float tile[32][33];
    const int z = blockIdx.z;
    const float* W = (z == 0) ? W0 : (z == 1) ? W1 : (z == 2) ? W2 : W3;
    __half* out = outbase + (size_t)z * D_DIM * D_DIM;
    const int tx = threadIdx.x, ty = threadIdx.y;
    const int x = blockIdx.x * 32 + tx, y0 = blockIdx.y * 32;
    #pragma unroll
    for (int i = 0; i < 4; i++)
        tile[ty + i * 8][tx] = W[(size_t)(y0 + ty + i * 8) * D_DIM + x];
    __syncthreads();
    #pragma unroll
    for (int i = 0; i < 4; i++) {
        int n = blockIdx.x * 32 + ty + i * 8;
        int k = y0 + tx;
        out[(size_t)n * D_DIM + k] = __float2half_rn(tile[tx][ty + i * 8]);
    }
}

// ---------------------------------------------------------------------------
// fp16 projection GEMM: 128x128 tile, BK=64, 2-stage (unchanged from R14)
// ---------------------------------------------------------------------------
#define PJ_B     18432
#define PJ_STG   36864
#define PJ_SMEM  (2 * PJ_STG)

__device__ __forceinline__ void proj_load(char* base, const __half* Ag,
                                          const __half* Bg, int bm, int bn,
                                          int k0, int t)
{
    #pragma unroll
    for (int j = 0; j < 4; j++) {
        int idx = j * 256 + t;
        int r = idx >> 3, c = idx & 7;
        cpa(base + r * 144 + c * 16,        Ag + (size_t)(bm + r) * D_DIM + k0 + c * 8);
        cpa(base + PJ_B + r * 144 + c * 16, Bg + (size_t)(bn + r) * D_DIM + k0 + c * 8);
    }
}

__device__ __forceinline__ void proj_mainloop(const __half* Ag, const __half* Bg,
                                              char* sm, int bm, int bn, int t,
                                              float acc[4][4][4])
{
    const int lane = t & 31, wid = t >> 5;
    const int wr = wid >> 2, wc = wid & 3;
    const int l15 = lane & 15, lhi = lane >> 4;
    const int brow = (lane & 7) + ((lane & 16) ? 8 : 0);
    const int bcol8 = (lane & 8) ? 8 : 0;

    proj_load(sm, Ag, Bg, bm, bn, 0, t);
    cp_commit();

    for (int c = 0; c < 16; c++) {
        if (c < 15) {
            proj_load(sm + ((c + 1) & 1) * PJ_STG, Ag, Bg, bm, bn, (c + 1) * 64, t);
            cp_commit();
            cp_wait<1>();
        } else {
            cp_wait<0>();
        }
        __syncthreads();
        const __half* A = (const __half*)(sm + (c & 1) * PJ_STG);
        const __half* B = (const __half*)(sm + (c & 1) * PJ_STG + PJ_B);
        #pragma unroll
        for (int kg = 0; kg < 4; kg++) {
            uint32_t af[4][4], bf[2][4];
            #pragma unroll
            for (int mi = 0; mi < 4; mi++)
                ldm4(af[mi], smem_u32(&A[(wr * 64 + mi * 16 + l15) * 72 + kg * 16 + lhi * 8]));
            #pragma unroll
            for (int ng = 0; ng < 2; ng++)
                ldm4(bf[ng], smem_u32(&B[(wc * 32 + ng * 16 + brow) * 72 + kg * 16 + bcol8]));
            #pragma unroll
            for (int mi = 0; mi < 4; mi++)
                #pragma unroll
                for (int nj = 0; nj < 4; nj++) {
                    int ng = nj >> 1, fo = (nj & 1) * 2;
                    mma_fp16(acc[mi][nj], af[mi], bf[ng][fo], bf[ng][fo + 1]);
                }
        }
        __syncthreads();
    }
}

__global__ __launch_bounds__(256, 2)
void proj_qkv(const float* __restrict__ bq, const float* __restrict__ bk,
              const float* __restrict__ bv, const int* __restrict__ stypes,
              const float* __restrict__ sw)
{
    extern __shared__ __align__(16) char sm[];
    const int t = threadIdx.x, lane = t & 31, wid = t >> 5;
    const int wr = wid >> 2, wc = wid & 3;
    const int g = lane >> 2, t4 = lane & 3;
    const int bm = blockIdx.y * 128, bn = blockIdx.x * 128;
    const int z = blockIdx.z;

    const float* bias = (z == 0) ? bq : (z == 1) ? bk : bv;
    const __half* Bg = g_wt + (size_t)z * D_DIM * D_DIM;

    float acc[4][4][4] = {};
    proj_mainloop(g_hid, Bg, sm, bm, bn, t, acc);

    const float QSCALE = 0.125f * 1.4426950408889634f;  // exp2 form
    #pragma unroll
    for (int mi = 0; mi < 4; mi++)
        #pragma unroll
        for (int nj = 0; nj < 4; nj++) {
            int col = bn + wc * 32 + nj * 8 + t4 * 2;
            float b0 = bias[col], b1 = bias[col + 1];
            #pragma unroll
            for (int hh = 0; hh < 2; hh++) {
                int row = bm + wr * 64 + mi * 16 + g + hh * 8;
                float s = 1.0f;
                if (z == 0) s = sw[stypes[row] * N_H + (col >> 6)] * QSCALE;
                float x = (acc[mi][nj][hh * 2]     + b0) * s;
                float y = (acc[mi][nj][hh * 2 + 1] + b1) * s;
                if (z < 2) {
                    __half* O = (z == 0) ? g_q : g_k;
                    *(__half2*)(O + (size_t)row * D_DIM + col) = __floats2half2_rn(x, y);
                } else {
                    int b = row >> 11, tok = row & 2047;
                    int hd = col >> 6, dl = col & 63;
                    size_t base = ((size_t)((b << 4) + hd) * 64 + dl) * S_LEN;
                    g_vt[base + tok]         = __float2half_rn(x);
                    g_vt[base + S_LEN + tok] = __float2half_rn(y);
                }
            }
        }
}

__global__ __launch_bounds__(256, 2)
void proj_o(const float* __restrict__ bias, float* __restrict__ Cf)
{
    extern __shared__ __align__(16) char sm[];
    const int t = threadIdx.x, lane = t & 31, wid = t >> 5;
    const int wr = wid >> 2, wc = wid & 3;
    const int g = lane >> 2, t4 = lane & 3;
    const int bm = blockIdx.y * 128, bn = blockIdx.x * 128;

    float acc[4][4][4] = {};
    proj_mainloop(g_ctx, g_wt + (size_t)3 * D_DIM * D_DIM, sm, bm, bn, t, acc);

    #pragma unroll
    for (int mi = 0; mi < 4; mi++)
        #pragma unroll
        for (int nj = 0; nj < 4; nj++) {
            int col = bn + wc * 32 + nj * 8 + t4 * 2;
            float b0 = bias[col], b1 = bias[col + 1];
            #pragma unroll
            for (int hh = 0; hh < 2; hh++) {
                int row = bm + wr * 64 + mi * 16 + g + hh * 8;
                float2 o;
                o.x = acc[mi][nj][hh * 2]     + b0;
                o.y = acc[mi][nj][hh * 2 + 1] + b1;
                *(float2*)(Cf + (size_t)row * D_DIM + col) = o;
            }
        }
}

// ---------------------------------------------------------------------------
// flash_fp16: BM=64, 256 threads, 2 CTAs/SM.
// Pass 2: p fed DIRECTLY from QK accumulators into PV A-fragments (register
// identity) — no Ps smem round-trip, ONE sync per tile. Each warp accumulates
// a partial PV over its 32-token strip; 4 partials reduced via smem at end.
// ---------------------------------------------------------------------------
#define FL_K    0          // 2 x [128][72]h = 36864
#define FL_V    36864      // 2 x [64][136]h = 34816  (pass1: K buf2 here)
#define FL_Q    71680      // [64][72]h      = 9216   (Q stage)
#define FL_IL   80896      // float[64]
#define FL_MB   81408      // float[3][128]
#define FL_RED  82944      // float[4][64]
#define FL_SMEM 84224      // (final reduction reuses bytes [0, 65536))

__global__ __launch_bounds__(256, 2)
void flash_fp16(float* __restrict__ probs)
{
    extern __shared__ __align__(16) char sm[];
    const int t = threadIdx.x, lane = t & 31, wid = t >> 5;
    const int bh = blockIdx.y, b = bh >> 4, h = bh & 15;
    const int q0 = blockIdx.x * 64;
    const int g = lane >> 2, t4 = lane & 3;
    const int l15 = lane & 15, lhi = lane >> 4;
    const int brow = (lane & 7) + ((lane & 16) ? 8 : 0);
    const int bcol8 = (lane & 8) ? 8 : 0;

    float* il   = (float*)(sm + FL_IL);
    float* mb   = (float*)(sm + FL_MB);
    float* red  = (float*)(sm + FL_RED);

    const int wr = wid >> 2, wc = wid & 3;     // 32q strips (wr 0..1) x 32tok strips

    const float* mbg = g_mbias + b * S_LEN;

    auto kb1 = [&](int i) -> char* {           // pass-1 triple K buffers
        return sm + (i == 2 ? FL_V : FL_K + i * 18432);
    };

    // preload group A: Q + K(0) + mb(0)
    #pragma unroll
    for (int j = 0; j < 2; j++) {
        int idx = j * 256 + t;
        int r = idx >> 3, c = idx & 7;
        cpa(sm + FL_Q + r * 144 + c * 16,
            g_q + (size_t)(b * S_LEN + q0 + r) * D_DIM + h * 64 + c * 8);
    }
    #pragma unroll
    for (int j = 0; j < 4; j++) {
        int idx = j * 256 + t;
        int r = idx >> 3, c = idx & 7;
        cpa(kb1(0) + r * 144 + c * 16,
            g_k + (size_t)(b * S_LEN + r) * D_DIM + h * 64 + c * 8);
    }
    if (t < 32) cpa((char*)mb + t * 16, mbg + t * 4);
    cp_commit();
    // preload group B: K(1) + mb(1)
    #pragma unroll
    for (int j = 0; j < 4; j++) {
        int idx = j * 256 + t;
        int r = idx >> 3, c = idx & 7;
        cpa(kb1(1) + r * 144 + c * 16,
            g_k + (size_t)(b * S_LEN + 128 + r) * D_DIM + h * 64 + c * 8);
    }
    if (t < 32) cpa((char*)mb + 512 + t * 16, mbg + 128 + t * 4);
    cp_commit();

    cp_wait<1>();
    __syncthreads();

    // Q A-fragments -> registers
    uint32_t qf[4][2][4];
    {
        const __half* Qs = (const __half*)(sm + FL_Q);
        #pragma unroll
        for (int kg = 0; kg < 4; kg++)
            #pragma unroll
            for (int mi = 0; mi < 2; mi++)
                ldm4(qf[kg][mi],
                     smem_u32(&Qs[(wr * 32 + mi * 16 + l15) * 72 + kg * 16 + lhi * 8]));
    }

    float lp[2][2] = {};

    // =================== pass 1: row sums ===================
    for (int nt = 0; nt < 16; nt++) {
        if (nt > 0) {
            if (nt < 15) cp_wait<1>(); else cp_wait<0>();
            __syncthreads();
        }
        if (nt + 2 <= 15) {
            int dst = (nt + 2) % 3;
            #pragma unroll
            for (int j = 0; j < 4; j++) {
                int idx = j * 256 + t;
                int r = idx >> 3, c = idx & 7;
                cpa(kb1(dst) + r * 144 + c * 16,
                    g_k + (size_t)(b * S_LEN + (nt + 2) * 128 + r) * D_DIM + h * 64 + c * 8);
            }
            if (t < 32) cpa((char*)mb + dst * 512 + t * 16, mbg + (nt + 2) * 128 + t * 4);
            cp_commit();
        }

        const __half* K = (const __half*)kb1(nt % 3);
        const float* mbc = mb + (nt % 3) * 128;

        float acc[2][4][4];
        #pragma unroll
        for (int nj = 0; nj < 4; nj++) {
            int cl = wc * 32 + nj * 8 + t4 * 2;
            float m0 = mbc[cl], m1 = mbc[cl + 1];
            #pragma unroll
            for (int mi = 0; mi < 2; mi++) {
                acc[mi][nj][0] = m0; acc[mi][nj][1] = m1;
                acc[mi][nj][2] = m0; acc[mi][nj][3] = m1;
            }
        }
        #pragma unroll
        for (int kg = 0; kg < 4; kg++) {
            uint32_t bf[2][4];
            #pragma unroll
            for (int ng = 0; ng < 2; ng++)
                ldm4(bf[ng], smem_u32(&K[(wc * 32 + ng * 16 + brow) * 72 + kg * 16 + bcol8]));
            #pragma unroll
            for (int mi = 0; mi < 2; mi++)
                #pragma unroll
                for (int nj = 0; nj < 4; nj++) {
                    int ng = nj >> 1, fo = (nj & 1) * 2;
                    mma_fp16(acc[mi][nj], qf[kg][mi], bf[ng][fo], bf[ng][fo + 1]);
                }
        }

        #pragma unroll
        for (int mi = 0; mi < 2; mi++)
            #pragma unroll
            for (int hh = 0; hh < 2; hh++) {
                float s = 0.f;
                #pragma unroll
                for (int nj = 0; nj < 4; nj++)
                    s += exp2f(acc[mi][nj][hh * 2]) + exp2f(acc[mi][nj][hh * 2 + 1]);
                s += __shfl_xor_sync(0xffffffffu, s, 1);
                s += __shfl_xor_sync(0xffffffffu, s, 2);
                lp[mi][hh] += s;
            }
    }

    if (t4 == 0)
        #pragma unroll
        for (int mi = 0; mi < 2; mi++)
            #pragma unroll
            for (int hh = 0; hh < 2; hh++)
                red[wc * 64 + wr * 32 + mi * 16 + g + hh * 8] = lp[mi][hh];
    __syncthreads();
    if (t < 64)
        il[t] = -__log2f(red[t] + red[64 + t] + red[128 + t] + red[192 + t]);

    // preload pass 2: ONE group = K(0) + mb(0) + V(0)
    #pragma unroll
    for (int j = 0; j < 4; j++) {
        int idx = j * 256 + t;
        int r = idx >> 3, c = idx & 7;
        cpa(sm + FL_K + r * 144 + c * 16,
            g_k + (size_t)(b * S_LEN + r) * D_DIM + h * 64 + c * 8);
    }
    if (t < 32) cpa((char*)mb + t * 16, mbg + t * 4);
    #pragma unroll
    for (int j = 0; j < 4; j++) {
        int idx = j * 256 + t;
        int r = idx >> 4, c = idx & 15;
        cpa(sm + FL_V + r * 272 + c * 16,
            g_vt + ((size_t)bh * 64 + r) * S_LEN + c * 8);
    }
    cp_commit();

    // =================== pass 2: emit probs + partial PV ===================
    float accPV[2][8][4] = {};   // [mi][d n8-block][frag] over this warp's toks
    float* Pg = probs + ((size_t)bh * S_LEN + q0) * S_LEN;

    for (int nt = 0; nt < 16; nt++) {
        cp_wait<0>();        // K(nt)+V(nt)+mb(nt) arrived
        __syncthreads();     // all warps done with prev tile (buffers free)

        if (nt < 15) {
            #pragma unroll
            for (int j = 0; j < 4; j++) {
                int idx = j * 256 + t;
                int r = idx >> 3, c = idx & 7;
                cpa(sm + FL_K + ((nt + 1) & 1) * 18432 + r * 144 + c * 16,
                    g_k + (size_t)(b * S_LEN + (nt + 1) * 128 + r) * D_DIM + h * 64 + c * 8);
            }
            if (t < 32) cpa((char*)mb + ((nt + 1) & 1) * 512 + t * 16,
                            mbg + (nt + 1) * 128 + t * 4);
            #pragma unroll
            for (int j = 0; j < 4; j++) {
                int idx = j * 256 + t;
                int r = idx >> 4, c = idx & 15;
                cpa(sm + FL_V + ((nt + 1) & 1) * 17408 + r * 272 + c * 16,
                    g_vt + ((size_t)bh * 64 + r) * S_LEN + (nt + 1) * 128 + c * 8);
            }
            cp_commit();
        }

        const __half* K   = (const __half*)(sm + FL_K + (nt & 1) * 18432);
        const __half* Vc  = (const __half*)(sm + FL_V + (nt & 1) * 17408);
        const float* mbc  = mb + (nt & 1) * 128;

        float lr[2][2];
        #pragma unroll
        for (int mi = 0; mi < 2; mi++)
            #pragma unroll
            for (int hh = 0; hh < 2; hh++)
                lr[mi][hh] = il[wr * 32 + mi * 16 + g + hh * 8];

        // ---- QK (acc init = mask bias + log2(1/l)) ----
        float acc[2][4][4];
        #pragma unroll
        for (int nj = 0; nj < 4; nj++) {
            int cl = wc * 32 + nj * 8 + t4 * 2;
            float m0 = mbc[cl], m1 = mbc[cl + 1];
            #pragma unroll
            for (int mi = 0; mi < 2; mi++) {
                acc[mi][nj][0] = m0 + lr[mi][0];
                acc[mi][nj][1] = m1 + lr[mi][0];
                acc[mi][nj][2] = m0 + lr[mi][1];
                acc[mi][nj][3] = m1 + lr[mi][1];
            }
        }
        #pragma unroll
        for (int kg = 0; kg < 4; kg++) {
            uint32_t bf[2][4];
            #pragma unroll
            for (int ng = 0; ng < 2; ng++)
                ldm4(bf[ng], smem_u32(&K[(wc * 32 + ng * 16 + brow) * 72 + kg * 16 + bcol8]));
            #pragma unroll
            for (int mi = 0; mi < 2; mi++)
                #pragma unroll
                for (int nj = 0; nj < 4; nj++) {
                    int ng = nj >> 1, fo = (nj & 1) * 2;
                    mma_fp16(acc[mi][nj], qf[kg][mi], bf[ng][fo], bf[ng][fo + 1]);
                }
        }

        // ---- p = exp2(acc): STG probs, pack into PV A-fragments ----
        uint32_t pa[2][2][4];   // [mi][kg(tok16)][frag]
        #pragma unroll
        for (int mi = 0; mi < 2; mi++)
            #pragma unroll
            for (int nj = 0; nj < 4; nj++) {
                float p0 = exp2f(acc[mi][nj][0]);
                float p1 = exp2f(acc[mi][nj][1]);
                float p2 = exp2f(acc[mi][nj][2]);
                float p3 = exp2f(acc[mi][nj][3]);
                int r0 = wr * 32 + mi * 16 + g;
                int cl = wc * 32 + nj * 8 + t4 * 2;
                stg_cs2(Pg + (size_t)r0 * S_LEN + nt * 128 + cl, p0, p1);
                stg_cs2(Pg + (size_t)(r0 + 8) * S_LEN + nt * 128 + cl, p2, p3);
                int kg = nj >> 1, half = (nj & 1) * 2;
                pa[mi][kg][half]     = packh2(p0, p1);
                pa[mi][kg][half + 1] = packh2(p2, p3);
            }

        // ---- partial PV over this warp's 32-token strip ----
        #pragma unroll
        for (int kg = 0; kg < 2; kg++)
            #pragma unroll
            for (int dg = 0; dg < 4; dg++) {
                uint32_t bf[4];
                ldm4(bf, smem_u32(&Vc[(dg * 16 + brow) * 136 + wc * 32 + kg * 16 + bcol8]));
                #pragma unroll
                for (int mi = 0; mi < 2; mi++) {
                    mma_fp16(accPV[mi][dg * 2],     pa[mi][kg], bf[0], bf[1]);
                    mma_fp16(accPV[mi][dg * 2 + 1], pa[mi][kg], bf[2], bf[3]);
                }
            }
        // no trailing sync: next tile's top sync protects buffer reuse
    }

    // ---- cross-warp PV reduction (4 token-strips) + ctx write ----
    __syncthreads();                       // all PV MMAs done; smem reusable
    float* buf = (float*)sm;               // buf[wc][64 q][64 d] = 64 KB
    #pragma unroll
    for (int mi = 0; mi < 2; mi++)
        #pragma unroll
        for (int n8 = 0; n8 < 8; n8++) {
            int q = wr * 32 + mi * 16 + g;
            int d = n8 * 8 + t4 * 2;
            float* bb = buf + wc * 4096;
            *(float2*)&bb[q * 64 + d]       = make_float2(accPV[mi][n8][0], accPV[mi][n8][1]);
            *(float2*)&bb[(q + 8) * 64 + d] = make_float2(accPV[mi][n8][2], accPV[mi][n8][3]);
        }
    __syncthreads();
    #pragma unroll
    for (int i = 0; i < 8; i++) {
        int e = t * 2 + i * 512;           // 2 consecutive elems per thread
        int q = e >> 6, d = e & 63;
        float2 s0 = *(float2*)&buf[q * 64 + d];
        float2 s1 = *(float2*)&buf[4096 + q * 64 + d];
        float2 s2 = *(float2*)&buf[8192 + q * 64 + d];
        float2 s3 = *(float2*)&buf[12288 + q * 64 + d];
        float x = s0.x + s1.x + s2.x + s3.x;
        float y = s0.y + s1.y + s2.y + s3.y;
        *(__half2*)(g_ctx + (size_t)(b * S_LEN + q0 + q) * D_DIM + h * 64 + d) =
            __floats2half2_rn(x, y);
    }
}

// ---------------------------------------------------------------------------
extern "C" void kernel_launch(void* const* d_in, const int* in_sizes, int n_in,
                              void* d_out, int out_size)
{
    (void)in_sizes; (void)n_in; (void)out_size;

    const float* hidden = (const float*)d_in[0];
    const int*   mask   = (const int*)  d_in[1];
    const int*   stypes = (const int*)  d_in[2];
    const float* Wq = (const float*)d_in[3];
    const float* bq = (const float*)d_in[4];
    const float* Wk = (const float*)d_in[5];
    const float* bk = (const float*)d_in[6];
    const float* Wv = (const float*)d_in[7];
    const float* bv = (const float*)d_in[8];
    const float* Wo = (const float*)d_in[9];
    const float* bo = (const float*)d_in[10];
    const float* sw = (const float*)d_in[11];

    float* out   = (float*)d_out;
    float* probs = out + (size_t)M_ROWS * D_DIM;

    __half *hidp, *wtp;
    float *mbp;
    cudaGetSymbolAddress((void**)&hidp, g_hid);
    cudaGetSymbolAddress((void**)&wtp,  g_wt);
    cudaGetSymbolAddress((void**)&mbp,  g_mbias);

    cudaFuncSetAttribute(proj_qkv,   cudaFuncAttributeMaxDynamicSharedMemorySize, PJ_SMEM);
    cudaFuncSetAttribute(proj_o,     cudaFuncAttributeMaxDynamicSharedMemorySize, PJ_SMEM);
    cudaFuncSetAttribute(flash_fp16, cudaFuncAttributeMaxDynamicSharedMemorySize, FL_SMEM);

    prep_hid<<<2064, 256>>>((const float4*)hidden, (uint4*)hidp, 524288,
                            mask, mbp, 2 * S_LEN);
    prep_w<<<dim3(32, 32, 4), dim3(32, 8)>>>(Wq, Wk, Wv, Wo, wtp);

    proj_qkv<<<dim3(8, 32, 3), 256, PJ_SMEM>>>(bq, bk, bv, stypes, sw);

    flash_fp16<<<dim3(32, 32), 256, FL_SMEM>>>(probs);

    proj_o<<<dim3(8, 32), 256, PJ_SMEM>>>(bo, out);
}

// round 16
// speedup vs baseline: 1.1204x; 1.1204x over previous
#include <cuda_runtime.h>
#include <cuda_fp16.h>
#include <math_constants.h>
#include <cstdint>

#define S_LEN  2048
#define D_DIM  1024
#define N_H    16
#define M_ROWS 4096

// ------------------------- device scratch (bss) ----------------------------
#define DEVBUF __device__ __align__(256)
DEVBUF __half g_hid[M_ROWS * D_DIM];       // fp16, natural [row][k]
DEVBUF __half g_wt [4 * D_DIM * D_DIM];    // W^T [n][k] fp16
DEVBUF __half g_q  [M_ROWS * D_DIM];       // [token][1024]
DEVBUF __half g_k  [M_ROWS * D_DIM];
DEVBUF __half g_vt [32 * 64 * S_LEN];      // [bh][d][token]
DEVBUF __half g_ctx[M_ROWS * D_DIM];
DEVBUF float  g_mbias[2 * S_LEN];          // mask ? 0 : -1e30

// ------------------------------ helpers ------------------------------------
__device__ __forceinline__ uint32_t smem_u32(const void* p) {
    return (uint32_t)__cvta_generic_to_shared(p);
}
__device__ __forceinline__ void ldm4(uint32_t* r, uint32_t a) {
    asm volatile("ldmatrix.sync.aligned.m8n8.x4.shared.b16 {%0,%1,%2,%3}, [%4];"
                 : "=r"(r[0]), "=r"(r[1]), "=r"(r[2]), "=r"(r[3]) : "r"(a));
}
__device__ __forceinline__ void mma_fp16(float* c, const uint32_t* a,
                                         uint32_t b0, uint32_t b1) {
    asm volatile("mma.sync.aligned.m16n8k16.row.col.f32.f16.f16.f32 "
                 "{%0,%1,%2,%3}, {%4,%5,%6,%7}, {%8,%9}, {%0,%1,%2,%3};"
                 : "+f"(c[0]), "+f"(c[1]), "+f"(c[2]), "+f"(c[3])
                 : "r"(a[0]), "r"(a[1]), "r"(a[2]), "r"(a[3]), "r"(b0), "r"(b1));
}
__device__ __forceinline__ void cpa(void* d, const void* s) {
    asm volatile("cp.async.cg.shared.global [%0], [%1], 16;"
                 :: "r"(smem_u32(d)), "l"(s));
}
__device__ __forceinline__ void cp_commit() { asm volatile("cp.async.commit_group;"); }
template<int N> __device__ __forceinline__ void cp_wait() {
    asm volatile("cp.async.wait_group %0;" :: "n"(N));
}
__device__ __forceinline__ void stg_cs2(float* p, float x, float y) {
    asm volatile("st.global.cs.v2.f32 [%0], {%1, %2};"
                 :: "l"(p), "f"(x), "f"(y) : "memory");
}

// ---------------------------------------------------------------------------
// prep: fp32 -> fp16 hidden (+ mask bias); transpose + fp16 weights
// ---------------------------------------------------------------------------
__global__ __launch_bounds__(256)
void prep_hid(const float4* __restrict__ in, uint4* __restrict__ out, int ng,
              const int* __restrict__ mask, float* __restrict__ mbias, int nb)
{
    int i = blockIdx.x * 256 + threadIdx.x;
    if (i < ng) {
        float4 v0 = in[i * 2], v1 = in[i * 2 + 1];
        __half2 h0 = __floats2half2_rn(v0.x, v0.y);
        __half2 h1 = __floats2half2_rn(v0.z, v0.w);
        __half2 h2 = __floats2half2_rn(v1.x, v1.y);
        __half2 h3 = __floats2half2_rn(v1.z, v1.w);
        uint4 o;
        o.x = *(uint32_t*)&h0; o.y = *(uint32_t*)&h1;
        o.z = *(uint32_t*)&h2; o.w = *(uint32_t*)&h3;
        out[i] = o;
    }
    int j = i - ng;
    if (j >= 0 && j < nb) mbias[j] = mask[j] ? 0.f : -1e30f;
}

__global__ __launch_bounds__(256)
void prep_w(const float* __restrict__ W0, const float* __restrict__ W1,
            const float* __restrict__ W2, const float* __restrict__ W3,
            __half* __restrict__ outbase)
{
    __shared__ float tile[32][33];
    const int z = blockIdx.z;
    const float* W = (z == 0) ? W0 : (z == 1) ? W1 : (z == 2) ? W2 : W3;
    __half* out = outbase + (size_t)z * D_DIM * D_DIM;
    const int tx = threadIdx.x, ty = threadIdx.y;
    const int x = blockIdx.x * 32 + tx, y0 = blockIdx.y * 32;
    #pragma unroll
    for (int i = 0; i < 4; i++)
        tile[ty + i * 8][tx] = W[(size_t)(y0 + ty + i * 8) * D_DIM + x];
    __syncthreads();
    #pragma unroll
    for (int i = 0; i < 4; i++) {
        int n = blockIdx.x * 32 + ty + i * 8;
        int k = y0 + tx;
        out[(size_t)n * D_DIM + k] = __float2half_rn(tile[tx][ty + i * 8]);
    }
}

// ---------------------------------------------------------------------------
// fp16 projection GEMM: 128x128 tile, BK=64, 2-stage cp.async pipeline.
// ---------------------------------------------------------------------------
#define PJ_B     18432
#define PJ_STG   36864
#define PJ_SMEM  (2 * PJ_STG)

__device__ __forceinline__ void proj_load(char* base, const __half* Ag,
                                          const __half* Bg, int bm, int bn,
                                          int k0, int t)
{
    #pragma unroll
    for (int j = 0; j < 4; j++) {
        int idx = j * 256 + t;
        int r = idx >> 3, c = idx & 7;
        cpa(base + r * 144 + c * 16,        Ag + (size_t)(bm + r) * D_DIM + k0 + c * 8);
        cpa(base + PJ_B + r * 144 + c * 16, Bg + (size_t)(bn + r) * D_DIM + k0 + c * 8);
    }
}

__device__ __forceinline__ void proj_mainloop(const __half* Ag, const __half* Bg,
                                              char* sm, int bm, int bn, int t,
                                              float acc[4][4][4])
{
    const int lane = t & 31, wid = t >> 5;
    const int wr = wid >> 2, wc = wid & 3;
    const int l15 = lane & 15, lhi = lane >> 4;
    const int brow = (lane & 7) + ((lane & 16) ? 8 : 0);
    const int bcol8 = (lane & 8) ? 8 : 0;

    proj_load(sm, Ag, Bg, bm, bn, 0, t);
    cp_commit();

    for (int c = 0; c < 16; c++) {
        if (c < 15) {
            proj_load(sm + ((c + 1) & 1) * PJ_STG, Ag, Bg, bm, bn, (c + 1) * 64, t);
            cp_commit();
            cp_wait<1>();
        } else {
            cp_wait<0>();
        }
        __syncthreads();
        const __half* A = (const __half*)(sm + (c & 1) * PJ_STG);
        const __half* B = (const __half*)(sm + (c & 1) * PJ_STG + PJ_B);
        #pragma unroll
        for (int kg = 0; kg < 4; kg++) {
            uint32_t af[4][4], bf[2][4];
            #pragma unroll
            for (int mi = 0; mi < 4; mi++)
                ldm4(af[mi], smem_u32(&A[(wr * 64 + mi * 16 + l15) * 72 + kg * 16 + lhi * 8]));
            #pragma unroll
            for (int ng = 0; ng < 2; ng++)
                ldm4(bf[ng], smem_u32(&B[(wc * 32 + ng * 16 + brow) * 72 + kg * 16 + bcol8]));
            #pragma unroll
            for (int mi = 0; mi < 4; mi++)
                #pragma unroll
                for (int nj = 0; nj < 4; nj++) {
                    int ng = nj >> 1, fo = (nj & 1) * 2;
                    mma_fp16(acc[mi][nj], af[mi], bf[ng][fo], bf[ng][fo + 1]);
                }
        }
        __syncthreads();
    }
}

__global__ __launch_bounds__(256, 2)
void proj_qkv(const float* __restrict__ bq, const float* __restrict__ bk,
              const float* __restrict__ bv, const int* __restrict__ stypes,
              const float* __restrict__ sw)
{
    extern __shared__ __align__(16) char sm[];
    const int t = threadIdx.x, lane = t & 31, wid = t >> 5;
    const int wr = wid >> 2, wc = wid & 3;
    const int g = lane >> 2, t4 = lane & 3;
    const int bm = blockIdx.y * 128, bn = blockIdx.x * 128;
    const int z = blockIdx.z;

    const float* bias = (z == 0) ? bq : (z == 1) ? bk : bv;
    const __half* Bg = g_wt + (size_t)z * D_DIM * D_DIM;

    float acc[4][4][4] = {};
    proj_mainloop(g_hid, Bg, sm, bm, bn, t, acc);

    const float QSCALE = 0.125f * 1.4426950408889634f;  // exp2 form
    #pragma unroll
    for (int mi = 0; mi < 4; mi++)
        #pragma unroll
        for (int nj = 0; nj < 4; nj++) {
            int col = bn + wc * 32 + nj * 8 + t4 * 2;
            float b0 = bias[col], b1 = bias[col + 1];
            #pragma unroll
            for (int hh = 0; hh < 2; hh++) {
                int row = bm + wr * 64 + mi * 16 + g + hh * 8;
                float s = 1.0f;
                if (z == 0) s = sw[stypes[row] * N_H + (col >> 6)] * QSCALE;
                float x = (acc[mi][nj][hh * 2]     + b0) * s;
                float y = (acc[mi][nj][hh * 2 + 1] + b1) * s;
                if (z < 2) {
                    __half* O = (z == 0) ? g_q : g_k;
                    *(__half2*)(O + (size_t)row * D_DIM + col) = __floats2half2_rn(x, y);
                } else {
                    int b = row >> 11, tok = row & 2047;
                    int hd = col >> 6, dl = col & 63;
                    size_t base = ((size_t)((b << 4) + hd) * 64 + dl) * S_LEN;
                    g_vt[base + tok]         = __float2half_rn(x);
                    g_vt[base + S_LEN + tok] = __float2half_rn(y);
                }
            }
        }
}

__global__ __launch_bounds__(256, 2)
void proj_o(const float* __restrict__ bias, float* __restrict__ Cf)
{
    extern __shared__ __align__(16) char sm[];
    const int t = threadIdx.x, lane = t & 31, wid = t >> 5;
    const int wr = wid >> 2, wc = wid & 3;
    const int g = lane >> 2, t4 = lane & 3;
    const int bm = blockIdx.y * 128, bn = blockIdx.x * 128;

    float acc[4][4][4] = {};
    proj_mainloop(g_ctx, g_wt + (size_t)3 * D_DIM * D_DIM, sm, bm, bn, t, acc);

    #pragma unroll
    for (int mi = 0; mi < 4; mi++)
        #pragma unroll
        for (int nj = 0; nj < 4; nj++) {
            int col = bn + wc * 32 + nj * 8 + t4 * 2;
            float b0 = bias[col], b1 = bias[col + 1];
            #pragma unroll
            for (int hh = 0; hh < 2; hh++) {
                int row = bm + wr * 64 + mi * 16 + g + hh * 8;
                float2 o;
                o.x = acc[mi][nj][hh * 2]     + b0;
                o.y = acc[mi][nj][hh * 2 + 1] + b1;
                *(float2*)(Cf + (size_t)row * D_DIM + col) = o;
            }
        }
}

// ---------------------------------------------------------------------------
// flash_fp16: BM=64 q rows, 256 threads, 2 CTAs/SM (R14 configuration).
// probs written with st.global.cs (streaming, evict-first).
// ---------------------------------------------------------------------------
#define FL_K    0          // 2 x [128][72]h = 36864
#define FL_V    36864      // 2 x [64][136]h = 34816  (pass1: K buf2 here)
#define FL_PS   71680      // [64][136]h     = 17408  (stages Q [64][72]h)
#define FL_IL   89088      // float[64]
#define FL_MB   89344      // float[3][128]
#define FL_RED  90880      // float[4][64]
#define FL_SMEM 92160

__global__ __launch_bounds__(256, 2)
void flash_fp16(float* __restrict__ probs)
{
    extern __shared__ __align__(16) char sm[];
    const int t = threadIdx.x, lane = t & 31, wid = t >> 5;
    const int bh = blockIdx.y, b = bh >> 4, h = bh & 15;
    const int q0 = blockIdx.x * 64;
    const int g = lane >> 2, t4 = lane & 3;
    const int l15 = lane & 15, lhi = lane >> 4;
    const int brow = (lane & 7) + ((lane & 16) ? 8 : 0);
    const int bcol8 = (lane & 8) ? 8 : 0;

    __half* Ps  = (__half*)(sm + FL_PS);
    float* il   = (float*)(sm + FL_IL);
    float* mb   = (float*)(sm + FL_MB);
    float* red  = (float*)(sm + FL_RED);

    const int wr = wid >> 2, wc = wid & 3;     // QK: 32q x 32tok strips (wr 0..1)
    const int wr2 = wid >> 1, wc2 = wid & 1;   // PV: 16q x 32d strips  (wr2 0..3)

    const float* mbg = g_mbias + b * S_LEN;

    auto kb1 = [&](int i) -> char* {           // pass-1 triple K buffers
        return sm + (i == 2 ? FL_V : FL_K + i * 18432);
    };

    // preload group A: Q (staged in Ps, pitch 72h, 64 rows) + K(0) + mb(0)
    #pragma unroll
    for (int j = 0; j < 2; j++) {
        int idx = j * 256 + t;
        int r = idx >> 3, c = idx & 7;
        cpa((char*)Ps + r * 144 + c * 16,
            g_q + (size_t)(b * S_LEN + q0 + r) * D_DIM + h * 64 + c * 8);
    }
    #pragma unroll
    for (int j = 0; j < 4; j++) {
        int idx = j * 256 + t;
        int r = idx >> 3, c = idx & 7;
        cpa(kb1(0) + r * 144 + c * 16,
            g_k + (size_t)(b * S_LEN + r) * D_DIM + h * 64 + c * 8);
    }
    if (t < 32) cpa((char*)mb + t * 16, mbg + t * 4);
    cp_commit();
    // preload group B: K(1) + mb(1)
    #pragma unroll
    for (int j = 0; j < 4; j++) {
        int idx = j * 256 + t;
        int r = idx >> 3, c = idx & 7;
        cpa(kb1(1) + r * 144 + c * 16,
            g_k + (size_t)(b * S_LEN + 128 + r) * D_DIM + h * 64 + c * 8);
    }
    if (t < 32) cpa((char*)mb + 512 + t * 16, mbg + 128 + t * 4);
    cp_commit();

    cp_wait<1>();
    __syncthreads();

    // Q A-fragments -> registers
    uint32_t qf[4][2][4];
    {
        const __half* Qs = (const __half*)Ps;
        #pragma unroll
        for (int kg = 0; kg < 4; kg++)
            #pragma unroll
            for (int mi = 0; mi < 2; mi++)
                ldm4(qf[kg][mi],
                     smem_u32(&Qs[(wr * 32 + mi * 16 + l15) * 72 + kg * 16 + lhi * 8]));
    }

    float lp[2][2] = {};

    // =================== pass 1: row sums ===================
    for (int nt = 0; nt < 16; nt++) {
        if (nt > 0) {
            if (nt < 15) cp_wait<1>(); else cp_wait<0>();
            __syncthreads();
        }
        if (nt + 2 <= 15) {
            int dst = (nt + 2) % 3;
            #pragma unroll
            for (int j = 0; j < 4; j++) {
                int idx = j * 256 + t;
                int r = idx >> 3, c = idx & 7;
                cpa(kb1(dst) + r * 144 + c * 16,
                    g_k + (size_t)(b * S_LEN + (nt + 2) * 128 + r) * D_DIM + h * 64 + c * 8);
            }
            if (t < 32) cpa((char*)mb + dst * 512 + t * 16, mbg + (nt + 2) * 128 + t * 4);
            cp_commit();
        }

        const __half* K = (const __half*)kb1(nt % 3);
        const float* mbc = mb + (nt % 3) * 128;

        float acc[2][4][4];
        #pragma unroll
        for (int nj = 0; nj < 4; nj++) {
            int cl = wc * 32 + nj * 8 + t4 * 2;
            float m0 = mbc[cl], m1 = mbc[cl + 1];
            #pragma unroll
            for (int mi = 0; mi < 2; mi++) {
                acc[mi][nj][0] = m0; acc[mi][nj][1] = m1;
                acc[mi][nj][2] = m0; acc[mi][nj][3] = m1;
            }
        }
        #pragma unroll
        for (int kg = 0; kg < 4; kg++) {
            uint32_t bf[2][4];
            #pragma unroll
            for (int ng = 0; ng < 2; ng++)
                ldm4(bf[ng], smem_u32(&K[(wc * 32 + ng * 16 + brow) * 72 + kg * 16 + bcol8]));
            #pragma unroll
            for (int mi = 0; mi < 2; mi++)
                #pragma unroll
                for (int nj = 0; nj < 4; nj++) {
                    int ng = nj >> 1, fo = (nj & 1) * 2;
                    mma_fp16(acc[mi][nj], qf[kg][mi], bf[ng][fo], bf[ng][fo + 1]);
                }
        }

        #pragma unroll
        for (int mi = 0; mi < 2; mi++)
            #pragma unroll
            for (int hh = 0; hh < 2; hh++) {
                float s = 0.f;
                #pragma unroll
                for (int nj = 0; nj < 4; nj++)
                    s += exp2f(acc[mi][nj][hh * 2]) + exp2f(acc[mi][nj][hh * 2 + 1]);
                s += __shfl_xor_sync(0xffffffffu, s, 1);
                s += __shfl_xor_sync(0xffffffffu, s, 2);
                lp[mi][hh] += s;
            }
    }

    if (t4 == 0)
        #pragma unroll
        for (int mi = 0; mi < 2; mi++)
            #pragma unroll
            for (int hh = 0; hh < 2; hh++)
                red[wc * 64 + wr * 32 + mi * 16 + g + hh * 8] = lp[mi][hh];
    __syncthreads();
    if (t < 64)
        il[t] = -__log2f(red[t] + red[64 + t] + red[128 + t] + red[192 + t]);

    // preload pass 2: ONE group = K(0) + mb(0) + V(0)
    #pragma unroll
    for (int j = 0; j < 4; j++) {
        int idx = j * 256 + t;
        int r = idx >> 3, c = idx & 7;
        cpa(sm + FL_K + r * 144 + c * 16,
            g_k + (size_t)(b * S_LEN + r) * D_DIM + h * 64 + c * 8);
    }
    if (t < 32) cpa((char*)mb + t * 16, mbg + t * 4);
    #pragma unroll
    for (int j = 0; j < 4; j++) {
        int idx = j * 256 + t;
        int r = idx >> 4, c = idx & 15;
        cpa(sm + FL_V + r * 272 + c * 16,
            g_vt + ((size_t)bh * 64 + r) * S_LEN + c * 8);
    }
    cp_commit();

    // =================== pass 2: emit probs + PV ===================
    float accPV[4][4] = {};
    float* Pg = probs + ((size_t)bh * S_LEN + q0) * S_LEN;

    for (int nt = 0; nt < 16; nt++) {
        cp_wait<0>();
        __syncthreads();

        if (nt < 15) {
            #pragma unroll
            for (int j = 0; j < 4; j++) {
                int idx = j * 256 + t;
                int r = idx >> 3, c = idx & 7;
                cpa(sm + FL_K + ((nt + 1) & 1) * 18432 + r * 144 + c * 16,
                    g_k + (size_t)(b * S_LEN + (nt + 1) * 128 + r) * D_DIM + h * 64 + c * 8);
            }
            if (t < 32) cpa((char*)mb + ((nt + 1) & 1) * 512 + t * 16,
                            mbg + (nt + 1) * 128 + t * 4);
            #pragma unroll
            for (int j = 0; j < 4; j++) {
                int idx = j * 256 + t;
                int r = idx >> 4, c = idx & 15;
                cpa(sm + FL_V + ((nt + 1) & 1) * 17408 + r * 272 + c * 16,
                    g_vt + ((size_t)bh * 64 + r) * S_LEN + (nt + 1) * 128 + c * 8);
            }
            cp_commit();
        }

        const __half* K   = (const __half*)(sm + FL_K + (nt & 1) * 18432);
        const __half* Vc  = (const __half*)(sm + FL_V + (nt & 1) * 17408);
        const float* mbc  = mb + (nt & 1) * 128;

        float lr[2][2];
        #pragma unroll
        for (int mi = 0; mi < 2; mi++)
            #pragma unroll
            for (int hh = 0; hh < 2; hh++)
                lr[mi][hh] = il[wr * 32 + mi * 16 + g + hh * 8];

        float acc[2][4][4];
        #pragma unroll
        for (int nj = 0; nj < 4; nj++) {
            int cl = wc * 32 + nj * 8 + t4 * 2;
            float m0 = mbc[cl], m1 = mbc[cl + 1];
            #pragma unroll
            for (int mi = 0; mi < 2; mi++) {
                acc[mi][nj][0] = m0 + lr[mi][0];
                acc[mi][nj][1] = m1 + lr[mi][0];
                acc[mi][nj][2] = m0 + lr[mi][1];
                acc[mi][nj][3] = m1 + lr[mi][1];
            }
        }
        #pragma unroll
        for (int kg = 0; kg < 4; kg++) {
            uint32_t bf[2][4];
            #pragma unroll
            for (int ng = 0; ng < 2; ng++)
                ldm4(bf[ng], smem_u32(&K[(wc * 32 + ng * 16 + brow) * 72 + kg * 16 + bcol8]));
            #pragma unroll
            for (int mi = 0; mi < 2; mi++)
                #pragma unroll
                for (int nj = 0; nj < 4; nj++) {
                    int ng = nj >> 1, fo = (nj & 1) * 2;
                    mma_fp16(acc[mi][nj], qf[kg][mi], bf[ng][fo], bf[ng][fo + 1]);
                }
        }

        // p = exp2(acc): streaming-write fp32 probs, fp16 to Ps
        #pragma unroll
        for (int mi = 0; mi < 2; mi++)
            #pragma unroll
            for (int hh = 0; hh < 2; hh++) {
                int r = wr * 32 + mi * 16 + g + hh * 8;
                #pragma unroll
                for (int nj = 0; nj < 4; nj++) {
                    int cl = wc * 32 + nj * 8 + t4 * 2;
                    float p0 = exp2f(acc[mi][nj][hh * 2]);
                    float p1 = exp2f(acc[mi][nj][hh * 2 + 1]);
                    stg_cs2(Pg + (size_t)r * S_LEN + nt * 128 + cl, p0, p1);
                    *(__half2*)(Ps + r * 136 + cl) = __floats2half2_rn(p0, p1);
                }
            }

        __syncthreads();     // Ps visible; V(nt) resident

        // ---- PV (ldmatrix frags) ----
        #pragma unroll
        for (int kg = 0; kg < 8; kg++) {
            uint32_t af[4], bf[2][4];
            ldm4(af, smem_u32(&Ps[(wr2 * 16 + l15) * 136 + kg * 16 + lhi * 8]));
            #pragma unroll
            for (int ng = 0; ng < 2; ng++)
                ldm4(bf[ng], smem_u32(&Vc[(wc2 * 32 + ng * 16 + brow) * 136 + kg * 16 + bcol8]));
            #pragma unroll
            for (int nj = 0; nj < 4; nj++) {
                int ng = nj >> 1, fo = (nj & 1) * 2;
                mma_fp16(accPV[nj], af, bf[ng][fo], bf[ng][fo + 1]);
            }
        }
        // no trailing sync: next tile's top sync protects buffer reuse
    }

    // ---- ctx write (fp16) ----
    #pragma unroll
    for (int nj = 0; nj < 4; nj++) {
        int col = h * 64 + wc2 * 32 + nj * 8 + t4 * 2;
        #pragma unroll
        for (int hh = 0; hh < 2; hh++) {
            int row = b * S_LEN + q0 + wr2 * 16 + g + hh * 8;
            *(__half2*)(g_ctx + (size_t)row * D_DIM + col) =
                __floats2half2_rn(accPV[nj][hh * 2], accPV[nj][hh * 2 + 1]);
        }
    }
}

// ---------------------------------------------------------------------------
extern "C" void kernel_launch(void* const* d_in, const int* in_sizes, int n_in,
                              void* d_out, int out_size)
{
    (void)in_sizes; (void)n_in; (void)out_size;

    const float* hidden = (const float*)d_in[0];
    const int*   mask   = (const int*)  d_in[1];
    const int*   stypes = (const int*)  d_in[2];
    const float* Wq = (const float*)d_in[3];
    const float* bq = (const float*)d_in[4];
    const float* Wk = (const float*)d_in[5];
    const float* bk = (const float*)d_in[6];
    const float* Wv = (const float*)d_in[7];
    const float* bv = (const float*)d_in[8];
    const float* Wo = (const float*)d_in[9];
    const float* bo = (const float*)d_in[10];
    const float* sw = (const float*)d_in[11];

    float* out   = (float*)d_out;
    float* probs = out + (size_t)M_ROWS * D_DIM;

    __half *hidp, *wtp;
    float *mbp;
    cudaGetSymbolAddress((void**)&hidp, g_hid);
    cudaGetSymbolAddress((void**)&wtp,  g_wt);
    cudaGetSymbolAddress((void**)&mbp,  g_mbias);

    cudaFuncSetAttribute(proj_qkv,   cudaFuncAttributeMaxDynamicSharedMemorySize, PJ_SMEM);
    cudaFuncSetAttribute(proj_o,     cudaFuncAttributeMaxDynamicSharedMemorySize, PJ_SMEM);
    cudaFuncSetAttribute(flash_fp16, cudaFuncAttributeMaxDynamicSharedMemorySize, FL_SMEM);

    prep_hid<<<2064, 256>>>((const float4*)hidden, (uint4*)hidp, 524288,
                            mask, mbp, 2 * S_LEN);
    prep_w<<<dim3(32, 32, 4), dim3(32, 8)>>>(Wq, Wk, Wv, Wo, wtp);

    proj_qkv<<<dim3(8, 32, 3), 256, PJ_SMEM>>>(bq, bk, bv, stypes, sw);

    flash_fp16<<<dim3(32, 32), 256, FL_SMEM>>>(probs);

    proj_o<<<dim3(8, 32), 256, PJ_SMEM>>>(bo, out);
}

// round 17
// speedup vs baseline: 1.1294x; 1.0080x over previous
#include <cuda_runtime.h>
#include <cuda_fp16.h>
#include <math_constants.h>
#include <cstdint>

#define S_LEN  2048
#define D_DIM  1024
#define N_H    16
#define M_ROWS 4096

// ------------------------- device scratch (bss) ----------------------------
#define DEVBUF __device__ __align__(256)
DEVBUF __half g_hid[M_ROWS * D_DIM];       // fp16, natural [row][k]
DEVBUF __half g_wt [4 * D_DIM * D_DIM];    // W^T [n][k] fp16
DEVBUF __half g_q  [M_ROWS * D_DIM];       // [token][1024]
DEVBUF __half g_k  [M_ROWS * D_DIM];
DEVBUF __half g_vt [32 * 64 * S_LEN];      // [bh][d][token]
DEVBUF __half g_ctx[M_ROWS * D_DIM];
DEVBUF float  g_mbias[2 * S_LEN];          // mask ? 0 : -1e30

// ------------------------------ helpers ------------------------------------
__device__ __forceinline__ uint32_t smem_u32(const void* p) {
    return (uint32_t)__cvta_generic_to_shared(p);
}
__device__ __forceinline__ void ldm4(uint32_t* r, uint32_t a) {
    asm volatile("ldmatrix.sync.aligned.m8n8.x4.shared.b16 {%0,%1,%2,%3}, [%4];"
                 : "=r"(r[0]), "=r"(r[1]), "=r"(r[2]), "=r"(r[3]) : "r"(a));
}
__device__ __forceinline__ void mma_fp16(float* c, const uint32_t* a,
                                         uint32_t b0, uint32_t b1) {
    asm volatile("mma.sync.aligned.m16n8k16.row.col.f32.f16.f16.f32 "
                 "{%0,%1,%2,%3}, {%4,%5,%6,%7}, {%8,%9}, {%0,%1,%2,%3};"
                 : "+f"(c[0]), "+f"(c[1]), "+f"(c[2]), "+f"(c[3])
                 : "r"(a[0]), "r"(a[1]), "r"(a[2]), "r"(a[3]), "r"(b0), "r"(b1));
}
__device__ __forceinline__ void cpa(void* d, const void* s) {
    asm volatile("cp.async.cg.shared.global [%0], [%1], 16;"
                 :: "r"(smem_u32(d)), "l"(s));
}
__device__ __forceinline__ void cp_commit() { asm volatile("cp.async.commit_group;"); }
template<int N> __device__ __forceinline__ void cp_wait() {
    asm volatile("cp.async.wait_group %0;" :: "n"(N));
}
__device__ __forceinline__ void stg_cs2(float* p, float x, float y) {
    asm volatile("st.global.cs.v2.f32 [%0], {%1, %2};"
                 :: "l"(p), "f"(x), "f"(y) : "memory");
}
// one MUFU computes TWO exp2 (fp16) — used only for pass-1 row sums
__device__ __forceinline__ uint32_t ex2_h2(float x, float y) {
    __half2 h = __floats2half2_rn(x, y);
    uint32_t r;
    asm("ex2.approx.f16x2 %0, %1;" : "=r"(r) : "r"(*(uint32_t*)&h));
    return r;
}

// ---------------------------------------------------------------------------
// prep: fp32 -> fp16 hidden (+ mask bias); transpose + fp16 weights
// ---------------------------------------------------------------------------
__global__ __launch_bounds__(256)
void prep_hid(const float4* __restrict__ in, uint4* __restrict__ out, int ng,
              const int* __restrict__ mask, float* __restrict__ mbias, int nb)
{
    int i = blockIdx.x * 256 + threadIdx.x;
    if (i < ng) {
        float4 v0 = in[i * 2], v1 = in[i * 2 + 1];
        __half2 h0 = __floats2half2_rn(v0.x, v0.y);
        __half2 h1 = __floats2half2_rn(v0.z, v0.w);
        __half2 h2 = __floats2half2_rn(v1.x, v1.y);
        __half2 h3 = __floats2half2_rn(v1.z, v1.w);
        uint4 o;
        o.x = *(uint32_t*)&h0; o.y = *(uint32_t*)&h1;
        o.z = *(uint32_t*)&h2; o.w = *(uint32_t*)&h3;
        out[i] = o;
    }
    int j = i - ng;
    if (j >= 0 && j < nb) mbias[j] = mask[j] ? 0.f : -1e30f;
}

__global__ __launch_bounds__(256)
void prep_w(const float* __restrict__ W0, const float* __restrict__ W1,
            const float* __restrict__ W2, const float* __restrict__ W3,
            __half* __restrict__ outbase)
{
    __shared__ float tile[32][33];
    const int z = blockIdx.z;
    const float* W = (z == 0) ? W0 : (z == 1) ? W1 : (z == 2) ? W2 : W3;
    __half* out = outbase + (size_t)z * D_DIM * D_DIM;
    const int tx = threadIdx.x, ty = threadIdx.y;
    const int x = blockIdx.x * 32 + tx, y0 = blockIdx.y * 32;
    #pragma unroll
    for (int i = 0; i < 4; i++)
        tile[ty + i * 8][tx] = W[(size_t)(y0 + ty + i * 8) * D_DIM + x];
    __syncthreads();
    #pragma unroll
    for (int i = 0; i < 4; i++) {
        int n = blockIdx.x * 32 + ty + i * 8;
        int k = y0 + tx;
        out[(size_t)n * D_DIM + k] = __float2half_rn(tile[tx][ty + i * 8]);
    }
}

// ---------------------------------------------------------------------------
// fp16 projection GEMM: 128x128 tile, BK=64, 2-stage cp.async pipeline.
// ---------------------------------------------------------------------------
#define PJ_B     18432
#define PJ_STG   36864
#define PJ_SMEM  (2 * PJ_STG)

__device__ __forceinline__ void proj_load(char* base, const __half* Ag,
                                          const __half* Bg, int bm, int bn,
                                          int k0, int t)
{
    #pragma unroll
    for (int j = 0; j < 4; j++) {
        int idx = j * 256 + t;
        int r = idx >> 3, c = idx & 7;
        cpa(base + r * 144 + c * 16,        Ag + (size_t)(bm + r) * D_DIM + k0 + c * 8);
        cpa(base + PJ_B + r * 144 + c * 16, Bg + (size_t)(bn + r) * D_DIM + k0 + c * 8);
    }
}

__device__ __forceinline__ void proj_mainloop(const __half* Ag, const __half* Bg,
                                              char* sm, int bm, int bn, int t,
                                              float acc[4][4][4])
{
    const int lane = t & 31, wid = t >> 5;
    const int wr = wid >> 2, wc = wid & 3;
    const int l15 = lane & 15, lhi = lane >> 4;
    const int brow = (lane & 7) + ((lane & 16) ? 8 : 0);
    const int bcol8 = (lane & 8) ? 8 : 0;

    proj_load(sm, Ag, Bg, bm, bn, 0, t);
    cp_commit();

    for (int c = 0; c < 16; c++) {
        if (c < 15) {
            proj_load(sm + ((c + 1) & 1) * PJ_STG, Ag, Bg, bm, bn, (c + 1) * 64, t);
            cp_commit();
            cp_wait<1>();
        } else {
            cp_wait<0>();
        }
        __syncthreads();
        const __half* A = (const __half*)(sm + (c & 1) * PJ_STG);
        const __half* B = (const __half*)(sm + (c & 1) * PJ_STG + PJ_B);
        #pragma unroll
        for (int kg = 0; kg < 4; kg++) {
            uint32_t af[4][4], bf[2][4];
            #pragma unroll
            for (int mi = 0; mi < 4; mi++)
                ldm4(af[mi], smem_u32(&A[(wr * 64 + mi * 16 + l15) * 72 + kg * 16 + lhi * 8]));
            #pragma unroll
            for (int ng = 0; ng < 2; ng++)
                ldm4(bf[ng], smem_u32(&B[(wc * 32 + ng * 16 + brow) * 72 + kg * 16 + bcol8]));
            #pragma unroll
            for (int mi = 0; mi < 4; mi++)
                #pragma unroll
                for (int nj = 0; nj < 4; nj++) {
                    int ng = nj >> 1, fo = (nj & 1) * 2;
                    mma_fp16(acc[mi][nj], af[mi], bf[ng][fo], bf[ng][fo + 1]);
                }
        }
        __syncthreads();
    }
}

__global__ __launch_bounds__(256, 2)
void proj_qkv(const float* __restrict__ bq, const float* __restrict__ bk,
              const float* __restrict__ bv, const int* __restrict__ stypes,
              const float* __restrict__ sw)
{
    extern __shared__ __align__(16) char sm[];
    const int t = threadIdx.x, lane = t & 31, wid = t >> 5;
    const int wr = wid >> 2, wc = wid & 3;
    const int g = lane >> 2, t4 = lane & 3;
    const int bm = blockIdx.y * 128, bn = blockIdx.x * 128;
    const int z = blockIdx.z;

    const float* bias = (z == 0) ? bq : (z == 1) ? bk : bv;
    const __half* Bg = g_wt + (size_t)z * D_DIM * D_DIM;

    float acc[4][4][4] = {};
    proj_mainloop(g_hid, Bg, sm, bm, bn, t, acc);

    const float QSCALE = 0.125f * 1.4426950408889634f;  // exp2 form
    #pragma unroll
    for (int mi = 0; mi < 4; mi++)
        #pragma unroll
        for (int nj = 0; nj < 4; nj++) {
            int col = bn + wc * 32 + nj * 8 + t4 * 2;
            float b0 = bias[col], b1 = bias[col + 1];
            #pragma unroll
            for (int hh = 0; hh < 2; hh++) {
                int row = bm + wr * 64 + mi * 16 + g + hh * 8;
                float s = 1.0f;
                if (z == 0) s = sw[stypes[row] * N_H + (col >> 6)] * QSCALE;
                float x = (acc[mi][nj][hh * 2]     + b0) * s;
                float y = (acc[mi][nj][hh * 2 + 1] + b1) * s;
                if (z < 2) {
                    __half* O = (z == 0) ? g_q : g_k;
                    *(__half2*)(O + (size_t)row * D_DIM + col) = __floats2half2_rn(x, y);
                } else {
                    int b = row >> 11, tok = row & 2047;
                    int hd = col >> 6, dl = col & 63;
                    size_t base = ((size_t)((b << 4) + hd) * 64 + dl) * S_LEN;
                    g_vt[base + tok]         = __float2half_rn(x);
                    g_vt[base + S_LEN + tok] = __float2half_rn(y);
                }
            }
        }
}

__global__ __launch_bounds__(256, 2)
void proj_o(const float* __restrict__ bias, float* __restrict__ Cf)
{
    extern __shared__ __align__(16) char sm[];
    const int t = threadIdx.x, lane = t & 31, wid = t >> 5;
    const int wr = wid >> 2, wc = wid & 3;
    const int g = lane >> 2, t4 = lane & 3;
    const int bm = blockIdx.y * 128, bn = blockIdx.x * 128;

    float acc[4][4][4] = {};
    proj_mainloop(g_ctx, g_wt + (size_t)3 * D_DIM * D_DIM, sm, bm, bn, t, acc);

    #pragma unroll
    for (int mi = 0; mi < 4; mi++)
        #pragma unroll
        for (int nj = 0; nj < 4; nj++) {
            int col = bn + wc * 32 + nj * 8 + t4 * 2;
            float b0 = bias[col], b1 = bias[col + 1];
            #pragma unroll
            for (int hh = 0; hh < 2; hh++) {
                int row = bm + wr * 64 + mi * 16 + g + hh * 8;
                float2 o;
                o.x = acc[mi][nj][hh * 2]     + b0;
                o.y = acc[mi][nj][hh * 2 + 1] + b1;
                *(float2*)(Cf + (size_t)row * D_DIM + col) = o;
            }
        }
}

// ---------------------------------------------------------------------------
// flash_fp16: BM=64 q rows, 256 threads, 2 CTAs/SM.
// Pass 1 uses ex2.approx.f16x2 (two exps per MUFU) for row sums;
// pass 2 keeps fp32 exp2f (probs precision). probs via st.global.cs.
// ---------------------------------------------------------------------------
#define FL_K    0          // 2 x [128][72]h = 36864
#define FL_V    36864      // 2 x [64][136]h = 34816  (pass1: K buf2 here)
#define FL_PS   71680      // [64][136]h     = 17408  (stages Q [64][72]h)
#define FL_IL   89088      // float[64]
#define FL_MB   89344      // float[3][128]
#define FL_RED  90880      // float[4][64]
#define FL_SMEM 92160

__global__ __launch_bounds__(256, 2)
void flash_fp16(float* __restrict__ probs)
{
    extern __shared__ __align__(16) char sm[];
    const int t = threadIdx.x, lane = t & 31, wid = t >> 5;
    const int bh = blockIdx.y, b = bh >> 4, h = bh & 15;
    const int q0 = blockIdx.x * 64;
    const int g = lane >> 2, t4 = lane & 3;
    const int l15 = lane & 15, lhi = lane >> 4;
    const int brow = (lane & 7) + ((lane & 16) ? 8 : 0);
    const int bcol8 = (lane & 8) ? 8 : 0;

    __half* Ps  = (__half*)(sm + FL_PS);
    float* il   = (float*)(sm + FL_IL);
    float* mb   = (float*)(sm + FL_MB);
    float* red  = (float*)(sm + FL_RED);

    const int wr = wid >> 2, wc = wid & 3;     // QK: 32q x 32tok strips (wr 0..1)
    const int wr2 = wid >> 1, wc2 = wid & 1;   // PV: 16q x 32d strips  (wr2 0..3)

    const float* mbg = g_mbias + b * S_LEN;

    auto kb1 = [&](int i) -> char* {           // pass-1 triple K buffers
        return sm + (i == 2 ? FL_V : FL_K + i * 18432);
    };

    // preload group A: Q (staged in Ps, pitch 72h, 64 rows) + K(0) + mb(0)
    #pragma unroll
    for (int j = 0; j < 2; j++) {
        int idx = j * 256 + t;
        int r = idx >> 3, c = idx & 7;
        cpa((char*)Ps + r * 144 + c * 16,
            g_q + (size_t)(b * S_LEN + q0 + r) * D_DIM + h * 64 + c * 8);
    }
    #pragma unroll
    for (int j = 0; j < 4; j++) {
        int idx = j * 256 + t;
        int r = idx >> 3, c = idx & 7;
        cpa(kb1(0) + r * 144 + c * 16,
            g_k + (size_t)(b * S_LEN + r) * D_DIM + h * 64 + c * 8);
    }
    if (t < 32) cpa((char*)mb + t * 16, mbg + t * 4);
    cp_commit();
    // preload group B: K(1) + mb(1)
    #pragma unroll
    for (int j = 0; j < 4; j++) {
        int idx = j * 256 + t;
        int r = idx >> 3, c = idx & 7;
        cpa(kb1(1) + r * 144 + c * 16,
            g_k + (size_t)(b * S_LEN + 128 + r) * D_DIM + h * 64 + c * 8);
    }
    if (t < 32) cpa((char*)mb + 512 + t * 16, mbg + 128 + t * 4);
    cp_commit();

    cp_wait<1>();
    __syncthreads();

    // Q A-fragments -> registers
    uint32_t qf[4][2][4];
    {
        const __half* Qs = (const __half*)Ps;
        #pragma unroll
        for (int kg = 0; kg < 4; kg++)
            #pragma unroll
            for (int mi = 0; mi < 2; mi++)
                ldm4(qf[kg][mi],
                     smem_u32(&Qs[(wr * 32 + mi * 16 + l15) * 72 + kg * 16 + lhi * 8]));
    }

    float lp[2][2] = {};

    // =================== pass 1: row sums (f16x2 exp) ===================
    for (int nt = 0; nt < 16; nt++) {
        if (nt > 0) {
            if (nt < 15) cp_wait<1>(); else cp_wait<0>();
            __syncthreads();
        }
        if (nt + 2 <= 15) {
            int dst = (nt + 2) % 3;
            #pragma unroll
            for (int j = 0; j < 4; j++) {
                int idx = j * 256 + t;
                int r = idx >> 3, c = idx & 7;
                cpa(kb1(dst) + r * 144 + c * 16,
                    g_k + (size_t)(b * S_LEN + (nt + 2) * 128 + r) * D_DIM + h * 64 + c * 8);
            }
            if (t < 32) cpa((char*)mb + dst * 512 + t * 16, mbg + (nt + 2) * 128 + t * 4);
            cp_commit();
        }

        const __half* K = (const __half*)kb1(nt % 3);
        const float* mbc = mb + (nt % 3) * 128;

        float acc[2][4][4];
        #pragma unroll
        for (int nj = 0; nj < 4; nj++) {
            int cl = wc * 32 + nj * 8 + t4 * 2;
            float m0 = mbc[cl], m1 = mbc[cl + 1];
            #pragma unroll
            for (int mi = 0; mi < 2; mi++) {
                acc[mi][nj][0] = m0; acc[mi][nj][1] = m1;
                acc[mi][nj][2] = m0; acc[mi][nj][3] = m1;
            }
        }
        #pragma unroll
        for (int kg = 0; kg < 4; kg++) {
            uint32_t bf[2][4];
            #pragma unroll
            for (int ng = 0; ng < 2; ng++)
                ldm4(bf[ng], smem_u32(&K[(wc * 32 + ng * 16 + brow) * 72 + kg * 16 + bcol8]));
            #pragma unroll
            for (int mi = 0; mi < 2; mi++)
                #pragma unroll
                for (int nj = 0; nj < 4; nj++) {
                    int ng = nj >> 1, fo = (nj & 1) * 2;
                    mma_fp16(acc[mi][nj], qf[kg][mi], bf[ng][fo], bf[ng][fo + 1]);
                }
        }

        #pragma unroll
        for (int mi = 0; mi < 2; mi++)
            #pragma unroll
            for (int hh = 0; hh < 2; hh++) {
                float s = 0.f;
                #pragma unroll
                for (int nj = 0; nj < 4; nj++) {
                    uint32_t e2 = ex2_h2(acc[mi][nj][hh * 2], acc[mi][nj][hh * 2 + 1]);
                    float2 fe = __half22float2(*(__half2*)&e2);
                    s += fe.x + fe.y;
                }
                s += __shfl_xor_sync(0xffffffffu, s, 1);
                s += __shfl_xor_sync(0xffffffffu, s, 2);
                lp[mi][hh] += s;
            }
    }

    if (t4 == 0)
        #pragma unroll
        for (int mi = 0; mi < 2; mi++)
            #pragma unroll
            for (int hh = 0; hh < 2; hh++)
                red[wc * 64 + wr * 32 + mi * 16 + g + hh * 8] = lp[mi][hh];
    __syncthreads();
    if (t < 64)
        il[t] = -__log2f(red[t] + red[64 + t] + red[128 + t] + red[192 + t]);

    // preload pass 2: ONE group = K(0) + mb(0) + V(0)
    #pragma unroll
    for (int j = 0; j < 4; j++) {
        int idx = j * 256 + t;
        int r = idx >> 3, c = idx & 7;
        cpa(sm + FL_K + r * 144 + c * 16,
            g_k + (size_t)(b * S_LEN + r) * D_DIM + h * 64 + c * 8);
    }
    if (t < 32) cpa((char*)mb + t * 16, mbg + t * 4);
    #pragma unroll
    for (int j = 0; j < 4; j++) {
        int idx = j * 256 + t;
        int r = idx >> 4, c = idx & 15;
        cpa(sm + FL_V + r * 272 + c * 16,
            g_vt + ((size_t)bh * 64 + r) * S_LEN + c * 8);
    }
    cp_commit();

    // =================== pass 2: emit probs + PV ===================
    float accPV[4][4] = {};
    float* Pg = probs + ((size_t)bh * S_LEN + q0) * S_LEN;

    for (int nt = 0; nt < 16; nt++) {
        cp_wait<0>();
        __syncthreads();

        if (nt < 15) {
            #pragma unroll
            for (int j = 0; j < 4; j++) {
                int idx = j * 256 + t;
                int r = idx >> 3, c = idx & 7;
                cpa(sm + FL_K + ((nt + 1) & 1) * 18432 + r * 144 + c * 16,
                    g_k + (size_t)(b * S_LEN + (nt + 1) * 128 + r) * D_DIM + h * 64 + c * 8);
            }
            if (t < 32) cpa((char*)mb + ((nt + 1) & 1) * 512 + t * 16,
                            mbg + (nt + 1) * 128 + t * 4);
            #pragma unroll
            for (int j = 0; j < 4; j++) {
                int idx = j * 256 + t;
                int r = idx >> 4, c = idx & 15;
                cpa(sm + FL_V + ((nt + 1) & 1) * 17408 + r * 272 + c * 16,
                    g_vt + ((size_t)bh * 64 + r) * S_LEN + (nt + 1) * 128 + c * 8);
            }
            cp_commit();
        }

        const __half* K   = (const __half*)(sm + FL_K + (nt & 1) * 18432);
        const __half* Vc  = (const __half*)(sm + FL_V + (nt & 1) * 17408);
        const float* mbc  = mb + (nt & 1) * 128;

        float lr[2][2];
        #pragma unroll
        for (int mi = 0; mi < 2; mi++)
            #pragma unroll
            for (int hh = 0; hh < 2; hh++)
                lr[mi][hh] = il[wr * 32 + mi * 16 + g + hh * 8];

        float acc[2][4][4];
        #pragma unroll
        for (int nj = 0; nj < 4; nj++) {
            int cl = wc * 32 + nj * 8 + t4 * 2;
            float m0 = mbc[cl], m1 = mbc[cl + 1];
            #pragma unroll
            for (int mi = 0; mi < 2; mi++) {
                acc[mi][nj][0] = m0 + lr[mi][0];
                acc[mi][nj][1] = m1 + lr[mi][0];
                acc[mi][nj][2] = m0 + lr[mi][1];
                acc[mi][nj][3] = m1 + lr[mi][1];
            }
        }
        #pragma unroll
        for (int kg = 0; kg < 4; kg++) {
            uint32_t bf[2][4];
            #pragma unroll
            for (int ng = 0; ng < 2; ng++)
                ldm4(bf[ng], smem_u32(&K[(wc * 32 + ng * 16 + brow) * 72 + kg * 16 + bcol8]));
            #pragma unroll
            for (int mi = 0; mi < 2; mi++)
                #pragma unroll
                for (int nj = 0; nj < 4; nj++) {
                    int ng = nj >> 1, fo = (nj & 1) * 2;
                    mma_fp16(acc[mi][nj], qf[kg][mi], bf[ng][fo], bf[ng][fo + 1]);
                }
        }

        // p = exp2(acc) fp32: streaming-write probs, fp16 to Ps
        #pragma unroll
        for (int mi = 0; mi < 2; mi++)
            #pragma unroll
            for (int hh = 0; hh < 2; hh++) {
                int r = wr * 32 + mi * 16 + g + hh * 8;
                #pragma unroll
                for (int nj = 0; nj < 4; nj++) {
                    int cl = wc * 32 + nj * 8 + t4 * 2;
                    float p0 = exp2f(acc[mi][nj][hh * 2]);
                    float p1 = exp2f(acc[mi][nj][hh * 2 + 1]);
                    stg_cs2(Pg + (size_t)r * S_LEN + nt * 128 + cl, p0, p1);
                    *(__half2*)(Ps + r * 136 + cl) = __floats2half2_rn(p0, p1);
                }
            }

        __syncthreads();     // Ps visible; V(nt) resident

        // ---- PV (ldmatrix frags) ----
        #pragma unroll
        for (int kg = 0; kg < 8; kg++) {
            uint32_t af[4], bf[2][4];
            ldm4(af, smem_u32(&Ps[(wr2 * 16 + l15) * 136 + kg * 16 + lhi * 8]));
            #pragma unroll
            for (int ng = 0; ng < 2; ng++)
                ldm4(bf[ng], smem_u32(&Vc[(wc2 * 32 + ng * 16 + brow) * 136 + kg * 16 + bcol8]));
            #pragma unroll
            for (int nj = 0; nj < 4; nj++) {
                int ng = nj >> 1, fo = (nj & 1) * 2;
                mma_fp16(accPV[nj], af, bf[ng][fo], bf[ng][fo + 1]);
            }
        }
        // no trailing sync: next tile's top sync protects buffer reuse
    }

    // ---- ctx write (fp16) ----
    #pragma unroll
    for (int nj = 0; nj < 4; nj++) {
        int col = h * 64 + wc2 * 32 + nj * 8 + t4 * 2;
        #pragma unroll
        for (int hh = 0; hh < 2; hh++) {
            int row = b * S_LEN + q0 + wr2 * 16 + g + hh * 8;
            *(__half2*)(g_ctx + (size_t)row * D_DIM + col) =
                __floats2half2_rn(accPV[nj][hh * 2], accPV[nj][hh * 2 + 1]);
        }
    }
}

// ---------------------------------------------------------------------------
extern "C" void kernel_launch(void* const* d_in, const int* in_sizes, int n_in,
                              void* d_out, int out_size)
{
    (void)in_sizes; (void)n_in; (void)out_size;

    const float* hidden = (const float*)d_in[0];
    const int*   mask   = (const int*)  d_in[1];
    const int*   stypes = (const int*)  d_in[2];
    const float* Wq = (const float*)d_in[3];
    const float* bq = (const float*)d_in[4];
    const float* Wk = (const float*)d_in[5];
    const float* bk = (const float*)d_in[6];
    const float* Wv = (const float*)d_in[7];
    const float* bv = (const float*)d_in[8];
    const float* Wo = (const float*)d_in[9];
    const float* bo = (const float*)d_in[10];
    const float* sw = (const float*)d_in[11];

    float* out   = (float*)d_out;
    float* probs = out + (size_t)M_ROWS * D_DIM;

    __half *hidp, *wtp;
    float *mbp;
    cudaGetSymbolAddress((void**)&hidp, g_hid);
    cudaGetSymbolAddress((void**)&wtp,  g_wt);
    cudaGetSymbolAddress((void**)&mbp,  g_mbias);

    cudaFuncSetAttribute(proj_qkv,   cudaFuncAttributeMaxDynamicSharedMemorySize, PJ_SMEM);
    cudaFuncSetAttribute(proj_o,     cudaFuncAttributeMaxDynamicSharedMemorySize, PJ_SMEM);
    cudaFuncSetAttribute(flash_fp16, cudaFuncAttributeMaxDynamicSharedMemorySize, FL_SMEM);

    prep_hid<<<2064, 256>>>((const float4*)hidden, (uint4*)hidp, 524288,
                            mask, mbp, 2 * S_LEN);
    prep_w<<<dim3(32, 32, 4), dim3(32, 8)>>>(Wq, Wk, Wv, Wo, wtp);

    proj_qkv<<<dim3(8, 32, 3), 256, PJ_SMEM>>>(bq, bk, bv, stypes, sw);

    flash_fp16<<<dim3(32, 32), 256, FL_SMEM>>>(probs);

    proj_o<<<dim3(8, 32), 256, PJ_SMEM>>>(bo, out);
}